// round 12
// baseline (speedup 1.0000x reference)
#include <cuda_runtime.h>
#include <math.h>

#define Bb 16
#define Hh 1024
#define Tt 4096
#define CD 8
#define CS 1024
#define HS 8            // H-splits for K1a
#define HC (Hh/HS)      // 128 h per block

static constexpr size_t OUT_N   = (size_t)Bb * Hh * Tt;          // 67108864
static constexpr size_t CL_OFF  = OUT_N;
static constexpr size_t CBL_OFF = OUT_N + 1;
static constexpr size_t IDX_OFF = OUT_N + 2;
static constexpr size_t PROJ_OFF = IDX_OFF + (size_t)Bb * Tt;
static constexpr size_t PROJ_N  = (size_t)Bb * CD * Tt;          // 524288

// packed-pair layout: per 4-token group (32 floats):
//   [ t0d0,t1d0, t0d1,t1d1, ... t0d7,t1d7,  t2d0,t3d0, ... t2d7,t3d7 ]
__device__ float g_pp[(size_t)HS * Bb * Tt * CD];  // 16.8MB
__device__ float g_quant[(size_t)Bb * CD * Tt];    // quant scratch [B][CD][T]
__device__ float g_partial[256];                   // per-block loss partials

// ---- packed f32x2 helpers ----
static __device__ __forceinline__ unsigned long long pk2(float lo, float hi) {
    unsigned long long r;
    asm("mov.b64 %0, {%1, %2};" : "=l"(r) : "f"(lo), "f"(hi));
    return r;
}
static __device__ __forceinline__ void upk2(unsigned long long v, float &lo, float &hi) {
    asm("mov.b64 {%0, %1}, %2;" : "=f"(lo), "=f"(hi) : "l"(v));
}
static __device__ __forceinline__ unsigned long long f2(unsigned long long a,
                                                        unsigned long long b,
                                                        unsigned long long c) {
    unsigned long long d;
    asm("fma.rn.f32x2 %0, %1, %2, %3;" : "=l"(d) : "l"(a), "l"(b), "l"(c));
    return d;
}
static __device__ __forceinline__ unsigned long long add2(unsigned long long a,
                                                          unsigned long long b) {
    unsigned long long d;
    asm("add.rn.f32x2 %0, %1, %2;" : "=l"(d) : "l"(a), "l"(b));
    return d;
}

// =====================================================================
// K1a: partial in-proj GEMV.
// grid 512 = b(16) x hs(8) x tc(4). block 256 threads, 4 tokens/thread.
// hidden loaded directly as ulonglong2 (f32 pairs pre-packed in memory);
// unroll 16 + launch_bounds(256,3) widens the LDG hoisting window.
// =====================================================================
__global__ void __launch_bounds__(256, 3) vq_k1a(
    const float* __restrict__ hidden,
    const float* __restrict__ w_in)
{
    __shared__ float wdup[HC * CD * 2];   // 8KB

    const int tid = threadIdx.x;
    const int blk = blockIdx.x;
    const int b   = blk >> 5;
    const int hs  = (blk >> 2) & 7;
    const int tc  = blk & 3;
    const int h0  = hs * HC;

    for (int i = tid; i < HC * CD; i += 256) {
        int h = i >> 3, d = i & 7;
        float w = w_in[(size_t)d * Hh + h0 + h];
        wdup[i * 2] = w; wdup[i * 2 + 1] = w;
    }
    __syncthreads();

    const int tbase = tc * 1024 + tid * 4;
    const float* hp = hidden + (size_t)b * Hh * Tt + (size_t)h0 * Tt + tbase;

    unsigned long long aA[8], aB[8];
#pragma unroll
    for (int d = 0; d < 8; d++) { aA[d] = 0ull; aB[d] = 0ull; }

#pragma unroll 16
    for (int h = 0; h < HC; h++) {
        ulonglong2 xv = *(const ulonglong2*)(hp + (size_t)h * Tt);
        unsigned long long xlo = xv.x;   // {x0, x1} packed
        unsigned long long xhi = xv.y;   // {x2, x3} packed
        ulonglong2 w01 = *(const ulonglong2*)(wdup + h * 16);
        ulonglong2 w23 = *(const ulonglong2*)(wdup + h * 16 + 4);
        ulonglong2 w45 = *(const ulonglong2*)(wdup + h * 16 + 8);
        ulonglong2 w67 = *(const ulonglong2*)(wdup + h * 16 + 12);
        // NOTE: xlo carries {t0,t1} and accumulates token-pair dots; each
        // FFMA2 multiplies by a duplicated weight {w,w}.
        aA[0] = f2(xlo, w01.x, aA[0]); aB[0] = f2(xhi, w01.x, aB[0]);
        aA[1] = f2(xlo, w01.y, aA[1]); aB[1] = f2(xhi, w01.y, aB[1]);
        aA[2] = f2(xlo, w23.x, aA[2]); aB[2] = f2(xhi, w23.x, aB[2]);
        aA[3] = f2(xlo, w23.y, aA[3]); aB[3] = f2(xhi, w23.y, aB[3]);
        aA[4] = f2(xlo, w45.x, aA[4]); aB[4] = f2(xhi, w45.x, aB[4]);
        aA[5] = f2(xlo, w45.y, aA[5]); aB[5] = f2(xhi, w45.y, aB[5]);
        aA[6] = f2(xlo, w67.x, aA[6]); aB[6] = f2(xhi, w67.x, aB[6]);
        aA[7] = f2(xlo, w67.y, aA[7]); aB[7] = f2(xhi, w67.y, aB[7]);
    }

    ulonglong2* pq = (ulonglong2*)(g_pp + (((size_t)hs * Bb + b) * Tt + tbase) * 8);
    ulonglong2 s;
    s.x = aA[0]; s.y = aA[1]; pq[0] = s;
    s.x = aA[2]; s.y = aA[3]; pq[1] = s;
    s.x = aA[4]; s.y = aA[5]; pq[2] = s;
    s.x = aA[6]; s.y = aA[7]; pq[3] = s;
    s.x = aB[0]; s.y = aB[1]; pq[4] = s;
    s.x = aB[2]; s.y = aB[3]; pq[5] = s;
    s.x = aB[4]; s.y = aB[5]; pq[6] = s;
    s.x = aB[6]; s.y = aB[7]; pq[7] = s;
}

// =====================================================================
// K1b: token-PAIR per thread. grid 256 = b(16) x chunk(16 of 256 tokens),
// block 128 threads = 128 pairs. (unchanged from R10)
// =====================================================================
__global__ void __launch_bounds__(128) vq_k1b(
    const float* __restrict__ b_in,
    const float* __restrict__ codebook,
    float* __restrict__ out)
{
    __shared__ float cbpf[8192];    // normalized codebook, pair-interleaved
    __shared__ float cseed[1024];   // 0.5*||cbn||^2, pair-interleaved
    __shared__ float inb[8];
    __shared__ float red[128];

    const int tid = threadIdx.x;
    const int blk = blockIdx.x;
    const int b   = blk >> 4;
    const int t0c = (blk & 15) << 8;

    if (tid < 8) inb[tid] = b_in[tid];

    for (int j = tid; j < CS; j += 128) {
        float4 c0 = __ldg((const float4*)(codebook + j * 8));
        float4 c1 = __ldg((const float4*)(codebook + j * 8 + 4));
        float c[8] = { c0.x, c0.y, c0.z, c0.w, c1.x, c1.y, c1.z, c1.w };
        float n2 = 0.f;
#pragma unroll
        for (int d = 0; d < 8; d++) n2 = fmaf(c[d], c[d], n2);
        float r = 1.0f / fmaxf(sqrtf(n2), 1e-12f);
        float cn2 = 0.f;
#pragma unroll
        for (int d = 0; d < 8; d++) { c[d] *= r; cn2 = fmaf(c[d], c[d], cn2); }
        int p = j >> 1, o = j & 1;
#pragma unroll
        for (int d = 0; d < 8; d++) cbpf[p * 16 + d * 2 + o] = c[d];
        cseed[p * 2 + o] = 0.5f * cn2;
    }
    __syncthreads();

    const int t0 = t0c + tid * 2;            // even token of this pair

    const size_t segoff = ((tid >> 1) * 32) + ((tid & 1) * 16);
    unsigned long long pacc[8];
#pragma unroll
    for (int d = 0; d < 8; d++) pacc[d] = 0ull;
#pragma unroll
    for (int hs = 0; hs < HS; hs++) {
        const float* base = g_pp + (((size_t)hs * Bb + b) * Tt + t0c) * 8 + segoff;
        ulonglong2 u0 = *(const ulonglong2*)(base);
        ulonglong2 u1 = *(const ulonglong2*)(base + 4);
        ulonglong2 u2 = *(const ulonglong2*)(base + 8);
        ulonglong2 u3 = *(const ulonglong2*)(base + 12);
        pacc[0] = add2(pacc[0], u0.x); pacc[1] = add2(pacc[1], u0.y);
        pacc[2] = add2(pacc[2], u1.x); pacc[3] = add2(pacc[3], u1.y);
        pacc[4] = add2(pacc[4], u2.x); pacc[5] = add2(pacc[5], u2.y);
        pacc[6] = add2(pacc[6], u3.x); pacc[7] = add2(pacc[7], u3.y);
    }
#pragma unroll
    for (int d = 0; d < 8; d++) pacc[d] = add2(pacc[d], pk2(inb[d], inb[d]));

#pragma unroll
    for (int d = 0; d < 8; d++) {
        float p0, p1; upk2(pacc[d], p0, p1);
        *(float2*)(out + PROJ_OFF + ((size_t)b * 8 + d) * Tt + t0) = make_float2(p0, p1);
    }

    unsigned long long n2p = 0ull;
#pragma unroll
    for (int d = 0; d < 8; d++) n2p = f2(pacc[d], pacc[d], n2p);
    float l20, l21; upk2(n2p, l20, l21);
    float rr0 = 1.0f / fmaxf(sqrtf(l20), 1e-12f);
    float rr1 = 1.0f / fmaxf(sqrtf(l21), 1e-12f);

    unsigned long long e0[8], e1[8];
#pragma unroll
    for (int d = 0; d < 8; d++) {
        float p0, p1; upk2(pacc[d], p0, p1);
        float a0 = p0 * rr0, a1 = p1 * rr1;
        e0[d] = pk2(a0, a0);
        e1[d] = pk2(a1, a1);
    }

    float best0 = -3.4e38f, best1 = -3.4e38f;
    int bi0 = 0, bi1 = 0;
#pragma unroll 2
    for (int p = 0; p < 512; p++) {
        unsigned long long seed = *(const unsigned long long*)(cseed + p * 2);
        ulonglong2 cA = *(const ulonglong2*)(cbpf + p * 16);
        ulonglong2 cB = *(const ulonglong2*)(cbpf + p * 16 + 4);
        ulonglong2 cC = *(const ulonglong2*)(cbpf + p * 16 + 8);
        ulonglong2 cD = *(const ulonglong2*)(cbpf + p * 16 + 12);
        unsigned long long xA = seed, xB = 0ull;   // token0
        unsigned long long yA = seed, yB = 0ull;   // token1
        xA = f2(e0[0], cA.x, xA); xB = f2(e0[1], cA.y, xB);
        yA = f2(e1[0], cA.x, yA); yB = f2(e1[1], cA.y, yB);
        xA = f2(e0[2], cB.x, xA); xB = f2(e0[3], cB.y, xB);
        yA = f2(e1[2], cB.x, yA); yB = f2(e1[3], cB.y, yB);
        xA = f2(e0[4], cC.x, xA); xB = f2(e0[5], cC.y, xB);
        yA = f2(e1[4], cC.x, yA); yB = f2(e1[5], cC.y, yB);
        xA = f2(e0[6], cD.x, xA); xB = f2(e0[7], cD.y, xB);
        yA = f2(e1[6], cD.x, yA); yB = f2(e1[7], cD.y, yB);
        unsigned long long ax = add2(xA, xB);
        unsigned long long ay = add2(yA, yB);
        float s0, s1; upk2(ax, s0, s1);
        if (s0 > best0) { best0 = s0; bi0 = 2 * p; }
        if (s1 > best0) { best0 = s1; bi0 = 2 * p + 1; }
        upk2(ay, s0, s1);
        if (s0 > best1) { best1 = s0; bi1 = 2 * p; }
        if (s1 > best1) { best1 = s1; bi1 = 2 * p + 1; }
    }

    float4 qa0 = __ldg((const float4*)(codebook + bi0 * 8));
    float4 qa1 = __ldg((const float4*)(codebook + bi0 * 8 + 4));
    float4 qb0 = __ldg((const float4*)(codebook + bi1 * 8));
    float4 qb1 = __ldg((const float4*)(codebook + bi1 * 8 + 4));
    float q0[8] = { qa0.x, qa0.y, qa0.z, qa0.w, qa1.x, qa1.y, qa1.z, qa1.w };
    float q1[8] = { qb0.x, qb0.y, qb0.z, qb0.w, qb1.x, qb1.y, qb1.z, qb1.w };

    float ls = 0.f;
#pragma unroll
    for (int d = 0; d < 8; d++) {
        float p0, p1; upk2(pacc[d], p0, p1);
        float d0 = p0 - q0[d], d1 = p1 - q1[d];
        ls = fmaf(d0, d0, ls); ls = fmaf(d1, d1, ls);
        *(float2*)(g_quant + ((size_t)b * 8 + d) * Tt + t0) = make_float2(q0[d], q1[d]);
    }
    *(float2*)(out + IDX_OFF + (size_t)b * Tt + t0) = make_float2((float)bi0, (float)bi1);

    red[tid] = ls;
    __syncthreads();
    for (int s = 64; s > 0; s >>= 1) {
        if (tid < s) red[tid] += red[tid + s];
        __syncthreads();
    }
    if (tid == 0) g_partial[blk] = red[0];
}

// =====================================================================
// K2: out = W_out * quant + b_out. grid 512 = b(16) x h-chunk(8 of 128)
// x t-chunk(4 of 1024). Plain float4 stores. Loss fused in block 0.
// (unchanged from R10)
// =====================================================================
__global__ void __launch_bounds__(256) vq_k2(
    const float* __restrict__ w_out,
    const float* __restrict__ b_out,
    float* __restrict__ out)
{
    extern __shared__ float sm[];
    float* qs  = sm;          // 8192
    float* wdf = sm + 8192;   // 2048
    float* bs  = sm + 10240;  // 128

    const int tid = threadIdx.x;
    const int blk = blockIdx.x;

    if (blk == 0) {
        double* sd = (double*)sm;
        sd[tid] = (tid < 256) ? (double)g_partial[tid] : 0.0;
        __syncthreads();
        for (int s = 128; s > 0; s >>= 1) {
            if (tid < s) sd[tid] += sd[tid + s];
            __syncthreads();
        }
        if (tid == 0) {
            float loss = (float)(sd[0] / (double)PROJ_N);
            out[CL_OFF]  = loss;
            out[CBL_OFF] = loss;
        }
        __syncthreads();
    }

    const int b  = blk >> 5;
    const int r  = blk & 31;
    const int h0 = (r >> 2) << 7;
    const int t0 = (r & 3) << 10;

    for (int i = tid; i < 8192; i += 256) {
        int d = i >> 10, tt = i & 1023;
        qs[i] = g_quant[((size_t)b * 8 + d) * Tt + t0 + tt];
    }
    for (int i = tid; i < 1024; i += 256) {
        float w = w_out[(size_t)(h0 + (i >> 3)) * 8 + (i & 7)];
        wdf[i * 2] = w; wdf[i * 2 + 1] = w;
    }
    if (tid < 128) bs[tid] = b_out[h0 + tid];
    __syncthreads();

    const int tt0 = tid * 4;
    unsigned long long qa[8], qb[8];
#pragma unroll
    for (int d = 0; d < 8; d++) {
        qa[d] = pk2(qs[d * 1024 + tt0],     qs[d * 1024 + tt0 + 1]);
        qb[d] = pk2(qs[d * 1024 + tt0 + 2], qs[d * 1024 + tt0 + 3]);
    }

    float* ob = out + ((size_t)b * Hh + h0) * Tt + t0 + tt0;
#pragma unroll 2
    for (int hl = 0; hl < 128; hl++) {
        float bh = bs[hl];
        unsigned long long aA = pk2(bh, bh);
        unsigned long long aB = aA;
        ulonglong2 wA = *(const ulonglong2*)(wdf + hl * 16);
        ulonglong2 wB = *(const ulonglong2*)(wdf + hl * 16 + 4);
        ulonglong2 wC = *(const ulonglong2*)(wdf + hl * 16 + 8);
        ulonglong2 wD = *(const ulonglong2*)(wdf + hl * 16 + 12);
        aA = f2(qa[0], wA.x, aA); aB = f2(qb[0], wA.x, aB);
        aA = f2(qa[1], wA.y, aA); aB = f2(qb[1], wA.y, aB);
        aA = f2(qa[2], wB.x, aA); aB = f2(qb[2], wB.x, aB);
        aA = f2(qa[3], wB.y, aA); aB = f2(qb[3], wB.y, aB);
        aA = f2(qa[4], wC.x, aA); aB = f2(qb[4], wC.x, aB);
        aA = f2(qa[5], wC.y, aA); aB = f2(qb[5], wC.y, aB);
        aA = f2(qa[6], wD.x, aA); aB = f2(qb[6], wD.x, aB);
        aA = f2(qa[7], wD.y, aA); aB = f2(qb[7], wD.y, aB);
        float o0, o1, o2, o3;
        upk2(aA, o0, o1); upk2(aB, o2, o3);
        *(float4*)(ob + (size_t)hl * Tt) = make_float4(o0, o1, o2, o3);
    }
}

extern "C" void kernel_launch(void* const* d_in, const int* in_sizes, int n_in,
                              void* d_out, int out_size)
{
    const float* hidden = (const float*)d_in[0];
    const float* w_in   = (const float*)d_in[1];
    const float* b_in   = (const float*)d_in[2];
    const float* w_out  = (const float*)d_in[3];
    const float* b_out  = (const float*)d_in[4];
    const float* cb     = (const float*)d_in[5];
    float* out = (float*)d_out;

    const int smem2 = 10368 * 4;   // 41472 B
    cudaFuncSetAttribute(vq_k2, cudaFuncAttributeMaxDynamicSharedMemorySize, smem2);

    vq_k1a<<<512, 256>>>(hidden, w_in);
    vq_k1b<<<256, 128>>>(b_in, cb, out);
    vq_k2<<<512, 256, smem2>>>(w_out, b_out, out);
}

// round 15
// speedup vs baseline: 1.0305x; 1.0305x over previous
#include <cuda_runtime.h>
#include <math.h>

#define Bb 16
#define Hh 1024
#define Tt 4096
#define CD 8
#define CS 1024
#define HS 8            // H-splits for K1a
#define HC (Hh/HS)      // 128 h per block

static constexpr size_t OUT_N   = (size_t)Bb * Hh * Tt;          // 67108864
static constexpr size_t CL_OFF  = OUT_N;
static constexpr size_t CBL_OFF = OUT_N + 1;
static constexpr size_t IDX_OFF = OUT_N + 2;
static constexpr size_t PROJ_OFF = IDX_OFF + (size_t)Bb * Tt;
static constexpr size_t PROJ_N  = (size_t)Bb * CD * Tt;          // 524288

// packed-pair layout: per 4-token group (32 floats):
//   [ t0d0,t1d0, t0d1,t1d1, ... t0d7,t1d7,  t2d0,t3d0, ... t2d7,t3d7 ]
__device__ float g_pp[(size_t)HS * Bb * Tt * CD];  // 16.8MB
__device__ float g_quant[(size_t)Bb * CD * Tt];    // quant scratch [B][CD][T]
__device__ float g_partial[256];                   // per-block loss partials

// ---- packed f32x2 helpers ----
static __device__ __forceinline__ unsigned long long pk2(float lo, float hi) {
    unsigned long long r;
    asm("mov.b64 %0, {%1, %2};" : "=l"(r) : "f"(lo), "f"(hi));
    return r;
}
static __device__ __forceinline__ void upk2(unsigned long long v, float &lo, float &hi) {
    asm("mov.b64 {%0, %1}, %2;" : "=f"(lo), "=f"(hi) : "l"(v));
}
static __device__ __forceinline__ unsigned long long f2(unsigned long long a,
                                                        unsigned long long b,
                                                        unsigned long long c) {
    unsigned long long d;
    asm("fma.rn.f32x2 %0, %1, %2, %3;" : "=l"(d) : "l"(a), "l"(b), "l"(c));
    return d;
}
static __device__ __forceinline__ unsigned long long add2(unsigned long long a,
                                                          unsigned long long b) {
    unsigned long long d;
    asm("add.rn.f32x2 %0, %1, %2;" : "=l"(d) : "l"(a), "l"(b));
    return d;
}

// =====================================================================
// K1a: partial in-proj GEMV.  (R10 config: unroll 8, occ 4; + direct
// ulonglong2 hidden loads)
// grid 512 = b(16) x hs(8) x tc(4). block 256 threads, 4 tokens/thread.
// =====================================================================
__global__ void __launch_bounds__(256, 4) vq_k1a(
    const float* __restrict__ hidden,
    const float* __restrict__ w_in)
{
    __shared__ float wdup[HC * CD * 2];   // 8KB

    const int tid = threadIdx.x;
    const int blk = blockIdx.x;
    const int b   = blk >> 5;
    const int hs  = (blk >> 2) & 7;
    const int tc  = blk & 3;
    const int h0  = hs * HC;

    for (int i = tid; i < HC * CD; i += 256) {
        int h = i >> 3, d = i & 7;
        float w = w_in[(size_t)d * Hh + h0 + h];
        wdup[i * 2] = w; wdup[i * 2 + 1] = w;
    }
    __syncthreads();

    const int tbase = tc * 1024 + tid * 4;
    const float* hp = hidden + (size_t)b * Hh * Tt + (size_t)h0 * Tt + tbase;

    unsigned long long aA[8], aB[8];
#pragma unroll
    for (int d = 0; d < 8; d++) { aA[d] = 0ull; aB[d] = 0ull; }

#pragma unroll 8
    for (int h = 0; h < HC; h++) {
        ulonglong2 xv = *(const ulonglong2*)(hp + (size_t)h * Tt);
        unsigned long long xlo = xv.x;   // {x0, x1} packed
        unsigned long long xhi = xv.y;   // {x2, x3} packed
        ulonglong2 w01 = *(const ulonglong2*)(wdup + h * 16);
        ulonglong2 w23 = *(const ulonglong2*)(wdup + h * 16 + 4);
        ulonglong2 w45 = *(const ulonglong2*)(wdup + h * 16 + 8);
        ulonglong2 w67 = *(const ulonglong2*)(wdup + h * 16 + 12);
        aA[0] = f2(xlo, w01.x, aA[0]); aB[0] = f2(xhi, w01.x, aB[0]);
        aA[1] = f2(xlo, w01.y, aA[1]); aB[1] = f2(xhi, w01.y, aB[1]);
        aA[2] = f2(xlo, w23.x, aA[2]); aB[2] = f2(xhi, w23.x, aB[2]);
        aA[3] = f2(xlo, w23.y, aA[3]); aB[3] = f2(xhi, w23.y, aB[3]);
        aA[4] = f2(xlo, w45.x, aA[4]); aB[4] = f2(xhi, w45.x, aB[4]);
        aA[5] = f2(xlo, w45.y, aA[5]); aB[5] = f2(xhi, w45.y, aB[5]);
        aA[6] = f2(xlo, w67.x, aA[6]); aB[6] = f2(xhi, w67.x, aB[6]);
        aA[7] = f2(xlo, w67.y, aA[7]); aB[7] = f2(xhi, w67.y, aB[7]);
    }

    ulonglong2* pq = (ulonglong2*)(g_pp + (((size_t)hs * Bb + b) * Tt + tbase) * 8);
    ulonglong2 s;
    s.x = aA[0]; s.y = aA[1]; pq[0] = s;
    s.x = aA[2]; s.y = aA[3]; pq[1] = s;
    s.x = aA[4]; s.y = aA[5]; pq[2] = s;
    s.x = aA[6]; s.y = aA[7]; pq[3] = s;
    s.x = aB[0]; s.y = aB[1]; pq[4] = s;
    s.x = aB[2]; s.y = aB[3]; pq[5] = s;
    s.x = aB[4]; s.y = aB[5]; pq[6] = s;
    s.x = aB[6]; s.y = aB[7]; pq[7] = s;
}

// =====================================================================
// K1b: token-PAIR per thread. grid 256 = b(16) x chunk(16 of 256 tokens),
// block 128 threads = 128 pairs. (unchanged)
// =====================================================================
__global__ void __launch_bounds__(128) vq_k1b(
    const float* __restrict__ b_in,
    const float* __restrict__ codebook,
    float* __restrict__ out)
{
    __shared__ float cbpf[8192];    // normalized codebook, pair-interleaved
    __shared__ float cseed[1024];   // 0.5*||cbn||^2, pair-interleaved
    __shared__ float inb[8];
    __shared__ float red[128];

    const int tid = threadIdx.x;
    const int blk = blockIdx.x;
    const int b   = blk >> 4;
    const int t0c = (blk & 15) << 8;

    if (tid < 8) inb[tid] = b_in[tid];

    for (int j = tid; j < CS; j += 128) {
        float4 c0 = __ldg((const float4*)(codebook + j * 8));
        float4 c1 = __ldg((const float4*)(codebook + j * 8 + 4));
        float c[8] = { c0.x, c0.y, c0.z, c0.w, c1.x, c1.y, c1.z, c1.w };
        float n2 = 0.f;
#pragma unroll
        for (int d = 0; d < 8; d++) n2 = fmaf(c[d], c[d], n2);
        float r = 1.0f / fmaxf(sqrtf(n2), 1e-12f);
        float cn2 = 0.f;
#pragma unroll
        for (int d = 0; d < 8; d++) { c[d] *= r; cn2 = fmaf(c[d], c[d], cn2); }
        int p = j >> 1, o = j & 1;
#pragma unroll
        for (int d = 0; d < 8; d++) cbpf[p * 16 + d * 2 + o] = c[d];
        cseed[p * 2 + o] = 0.5f * cn2;
    }
    __syncthreads();

    const int t0 = t0c + tid * 2;            // even token of this pair

    const size_t segoff = ((tid >> 1) * 32) + ((tid & 1) * 16);
    unsigned long long pacc[8];
#pragma unroll
    for (int d = 0; d < 8; d++) pacc[d] = 0ull;
#pragma unroll
    for (int hs = 0; hs < HS; hs++) {
        const float* base = g_pp + (((size_t)hs * Bb + b) * Tt + t0c) * 8 + segoff;
        ulonglong2 u0 = *(const ulonglong2*)(base);
        ulonglong2 u1 = *(const ulonglong2*)(base + 4);
        ulonglong2 u2 = *(const ulonglong2*)(base + 8);
        ulonglong2 u3 = *(const ulonglong2*)(base + 12);
        pacc[0] = add2(pacc[0], u0.x); pacc[1] = add2(pacc[1], u0.y);
        pacc[2] = add2(pacc[2], u1.x); pacc[3] = add2(pacc[3], u1.y);
        pacc[4] = add2(pacc[4], u2.x); pacc[5] = add2(pacc[5], u2.y);
        pacc[6] = add2(pacc[6], u3.x); pacc[7] = add2(pacc[7], u3.y);
    }
#pragma unroll
    for (int d = 0; d < 8; d++) pacc[d] = add2(pacc[d], pk2(inb[d], inb[d]));

#pragma unroll
    for (int d = 0; d < 8; d++) {
        float p0, p1; upk2(pacc[d], p0, p1);
        *(float2*)(out + PROJ_OFF + ((size_t)b * 8 + d) * Tt + t0) = make_float2(p0, p1);
    }

    unsigned long long n2p = 0ull;
#pragma unroll
    for (int d = 0; d < 8; d++) n2p = f2(pacc[d], pacc[d], n2p);
    float l20, l21; upk2(n2p, l20, l21);
    float rr0 = 1.0f / fmaxf(sqrtf(l20), 1e-12f);
    float rr1 = 1.0f / fmaxf(sqrtf(l21), 1e-12f);

    unsigned long long e0[8], e1[8];
#pragma unroll
    for (int d = 0; d < 8; d++) {
        float p0, p1; upk2(pacc[d], p0, p1);
        float a0 = p0 * rr0, a1 = p1 * rr1;
        e0[d] = pk2(a0, a0);
        e1[d] = pk2(a1, a1);
    }

    float best0 = -3.4e38f, best1 = -3.4e38f;
    int bi0 = 0, bi1 = 0;
#pragma unroll 2
    for (int p = 0; p < 512; p++) {
        unsigned long long seed = *(const unsigned long long*)(cseed + p * 2);
        ulonglong2 cA = *(const ulonglong2*)(cbpf + p * 16);
        ulonglong2 cB = *(const ulonglong2*)(cbpf + p * 16 + 4);
        ulonglong2 cC = *(const ulonglong2*)(cbpf + p * 16 + 8);
        ulonglong2 cD = *(const ulonglong2*)(cbpf + p * 16 + 12);
        unsigned long long xA = seed, xB = 0ull;   // token0
        unsigned long long yA = seed, yB = 0ull;   // token1
        xA = f2(e0[0], cA.x, xA); xB = f2(e0[1], cA.y, xB);
        yA = f2(e1[0], cA.x, yA); yB = f2(e1[1], cA.y, yB);
        xA = f2(e0[2], cB.x, xA); xB = f2(e0[3], cB.y, xB);
        yA = f2(e1[2], cB.x, yA); yB = f2(e1[3], cB.y, yB);
        xA = f2(e0[4], cC.x, xA); xB = f2(e0[5], cC.y, xB);
        yA = f2(e1[4], cC.x, yA); yB = f2(e1[5], cC.y, yB);
        xA = f2(e0[6], cD.x, xA); xB = f2(e0[7], cD.y, xB);
        yA = f2(e1[6], cD.x, yA); yB = f2(e1[7], cD.y, yB);
        unsigned long long ax = add2(xA, xB);
        unsigned long long ay = add2(yA, yB);
        float s0, s1; upk2(ax, s0, s1);
        if (s0 > best0) { best0 = s0; bi0 = 2 * p; }
        if (s1 > best0) { best0 = s1; bi0 = 2 * p + 1; }
        upk2(ay, s0, s1);
        if (s0 > best1) { best1 = s0; bi1 = 2 * p; }
        if (s1 > best1) { best1 = s1; bi1 = 2 * p + 1; }
    }

    float4 qa0 = __ldg((const float4*)(codebook + bi0 * 8));
    float4 qa1 = __ldg((const float4*)(codebook + bi0 * 8 + 4));
    float4 qb0 = __ldg((const float4*)(codebook + bi1 * 8));
    float4 qb1 = __ldg((const float4*)(codebook + bi1 * 8 + 4));
    float q0[8] = { qa0.x, qa0.y, qa0.z, qa0.w, qa1.x, qa1.y, qa1.z, qa1.w };
    float q1[8] = { qb0.x, qb0.y, qb0.z, qb0.w, qb1.x, qb1.y, qb1.z, qb1.w };

    float ls = 0.f;
#pragma unroll
    for (int d = 0; d < 8; d++) {
        float p0, p1; upk2(pacc[d], p0, p1);
        float d0 = p0 - q0[d], d1 = p1 - q1[d];
        ls = fmaf(d0, d0, ls); ls = fmaf(d1, d1, ls);
        *(float2*)(g_quant + ((size_t)b * 8 + d) * Tt + t0) = make_float2(q0[d], q1[d]);
    }
    *(float2*)(out + IDX_OFF + (size_t)b * Tt + t0) = make_float2((float)bi0, (float)bi1);

    red[tid] = ls;
    __syncthreads();
    for (int s = 64; s > 0; s >>= 1) {
        if (tid < s) red[tid] += red[tid + s];
        __syncthreads();
    }
    if (tid == 0) g_partial[blk] = red[0];
}

// =====================================================================
// K2: out = W_out * quant + b_out via smem staging + 1D TMA bulk stores.
// grid 512 = b(16) x h-chunk(8 of 128) x t-chunk(4 of 1024).
// 16 rounds of 8 h-rows; double-buffered 32KB smem output tiles drained
// by cp.async.bulk (no per-lane STG issue cost). Loss fused in block 0.
// smem floats: qs[8192] | wdf[2048] | bs[128] | obuf[2*8192]  (104.5KB)
// =====================================================================
__global__ void __launch_bounds__(256) vq_k2(
    const float* __restrict__ w_out,
    const float* __restrict__ b_out,
    float* __restrict__ out)
{
    extern __shared__ float sm[];
    float* qs   = sm;            // 8192
    float* wdf  = sm + 8192;     // 2048
    float* bs   = sm + 10240;    // 128
    float* obuf = sm + 10368;    // 16384 = 2 x (8 rows x 1024 t)

    const int tid = threadIdx.x;
    const int blk = blockIdx.x;

    if (blk == 0) {
        double* sd = (double*)sm;
        sd[tid] = (double)g_partial[tid];
        __syncthreads();
        for (int s = 128; s > 0; s >>= 1) {
            if (tid < s) sd[tid] += sd[tid + s];
            __syncthreads();
        }
        if (tid == 0) {
            float loss = (float)(sd[0] / (double)PROJ_N);
            out[CL_OFF]  = loss;
            out[CBL_OFF] = loss;
        }
        __syncthreads();
    }

    const int b  = blk >> 5;
    const int r5 = blk & 31;
    const int h0 = (r5 >> 2) << 7;
    const int t0 = (r5 & 3) << 10;

    for (int i = tid; i < 8192; i += 256) {
        int d = i >> 10, tt = i & 1023;
        qs[i] = g_quant[((size_t)b * 8 + d) * Tt + t0 + tt];
    }
    for (int i = tid; i < 1024; i += 256) {
        float w = w_out[(size_t)(h0 + (i >> 3)) * 8 + (i & 7)];
        wdf[i * 2] = w; wdf[i * 2 + 1] = w;
    }
    if (tid < 128) bs[tid] = b_out[h0 + tid];
    __syncthreads();

    const int tt0 = tid * 4;
    unsigned long long qa[8], qb[8];
#pragma unroll
    for (int d = 0; d < 8; d++) {
        qa[d] = pk2(qs[d * 1024 + tt0],     qs[d * 1024 + tt0 + 1]);
        qb[d] = pk2(qs[d * 1024 + tt0 + 2], qs[d * 1024 + tt0 + 3]);
    }

    const unsigned int obase =
        (unsigned int)__cvta_generic_to_shared(obuf);
    float* gbase = out + ((size_t)b * Hh + h0) * Tt + t0;

    for (int rr = 0; rr < 16; rr++) {
        const int buf = rr & 1;
        if (rr >= 2) {
            // buffer `buf` was committed in round rr-2; allow 1 group
            // (round rr-1) to remain in flight.
            if (tid == 0)
                asm volatile("cp.async.bulk.wait_group.read 1;" ::: "memory");
            __syncthreads();
        }
        float* ob = obuf + buf * 8192;
#pragma unroll
        for (int j = 0; j < 8; j++) {
            const int hl = rr * 8 + j;
            float bh = bs[hl];
            unsigned long long aA = pk2(bh, bh);
            unsigned long long aB = aA;
            ulonglong2 wA = *(const ulonglong2*)(wdf + hl * 16);
            ulonglong2 wB = *(const ulonglong2*)(wdf + hl * 16 + 4);
            ulonglong2 wC = *(const ulonglong2*)(wdf + hl * 16 + 8);
            ulonglong2 wD = *(const ulonglong2*)(wdf + hl * 16 + 12);
            aA = f2(qa[0], wA.x, aA); aB = f2(qb[0], wA.x, aB);
            aA = f2(qa[1], wA.y, aA); aB = f2(qb[1], wA.y, aB);
            aA = f2(qa[2], wB.x, aA); aB = f2(qb[2], wB.x, aB);
            aA = f2(qa[3], wB.y, aA); aB = f2(qb[3], wB.y, aB);
            aA = f2(qa[4], wC.x, aA); aB = f2(qb[4], wC.x, aB);
            aA = f2(qa[5], wC.y, aA); aB = f2(qb[5], wC.y, aB);
            aA = f2(qa[6], wD.x, aA); aB = f2(qb[6], wD.x, aB);
            aA = f2(qa[7], wD.y, aA); aB = f2(qb[7], wD.y, aB);
            float o0, o1, o2, o3;
            upk2(aA, o0, o1); upk2(aB, o2, o3);
            *(float4*)(ob + j * 1024 + tt0) = make_float4(o0, o1, o2, o3);
        }
        __syncthreads();
        if (tid == 0) {
            asm volatile("fence.proxy.async.shared::cta;" ::: "memory");
#pragma unroll
            for (int j = 0; j < 8; j++) {
                unsigned int saddr = obase + (unsigned int)(buf * 8192 + j * 1024) * 4u;
                float* gptr = gbase + (size_t)(rr * 8 + j) * Tt;
                asm volatile(
                    "cp.async.bulk.global.shared::cta.bulk_group [%0], [%1], %2;"
                    :: "l"(gptr), "r"(saddr), "r"(4096u) : "memory");
            }
            asm volatile("cp.async.bulk.commit_group;" ::: "memory");
        }
    }
    if (tid == 0)
        asm volatile("cp.async.bulk.wait_group 0;" ::: "memory");
    __syncthreads();
}

extern "C" void kernel_launch(void* const* d_in, const int* in_sizes, int n_in,
                              void* d_out, int out_size)
{
    const float* hidden = (const float*)d_in[0];
    const float* w_in   = (const float*)d_in[1];
    const float* b_in   = (const float*)d_in[2];
    const float* w_out  = (const float*)d_in[3];
    const float* b_out  = (const float*)d_in[4];
    const float* cb     = (const float*)d_in[5];
    float* out = (float*)d_out;

    const int smem2 = 26752 * 4;   // 107008 B
    cudaFuncSetAttribute(vq_k2, cudaFuncAttributeMaxDynamicSharedMemorySize, smem2);

    vq_k1a<<<512, 256>>>(hidden, w_in);
    vq_k1b<<<256, 128>>>(b_in, cb, out);
    vq_k2<<<512, 256, smem2>>>(w_out, b_out, out);
}